// round 11
// baseline (speedup 1.0000x reference)
#include <cuda_runtime.h>
#include <cuda.h>
#include <cuda_fp16.h>
#include <cstdint>
#include <math.h>

// LSTM cell: gates = [x|h0] @ [Wx|Wh]^T + b, fused elementwise epilogue.
// R11: persistent cg2 tcgen05 fp16 + TMEM PING-PONG. Each 256x512 tile is
// two 256x256 sub-tiles accumulated into TMEM halves; epilogue of one half
// overlaps MMA of the other. 6-stage 32KB TMA ring streams continuously.

#define BATCH 8192
#define HID   2048
#define KTOT  4096
#define NTILES 512      // 32 m-blocks x 16 n-blocks (of 128 hcols)
#define NPAIRS 74

#if defined(__CUDA_ARCH__) && defined(__CUDA_ARCH_FEAT_SM103_ALL)
#define HAS_TCGEN05 1
#else
#define HAS_TCGEN05 0
#endif

__device__ __forceinline__ uint32_t f2tf32(float x) {
    uint32_t u; asm("cvt.rna.tf32.f32 %0, %1;" : "=r"(u) : "f"(x)); return u;
}
__device__ __forceinline__ float ex2a(float x) {
    float y; asm("ex2.approx.f32 %0, %1;" : "=f"(y) : "f"(x)); return y;
}
__device__ __forceinline__ float rcpa(float x) {
    float y; asm("rcp.approx.f32 %0, %1;" : "=f"(y) : "f"(x)); return y;
}
__device__ __forceinline__ float fsig(float x) {
    return rcpa(1.0f + ex2a(-1.4426950408889634f * x));
}
__device__ __forceinline__ float ftanh(float x) {
    return fmaf(2.0f, rcpa(1.0f + ex2a(-2.8853900817779268f * x)), -1.0f);
}

// -------- scratch (module-load allocated) --------
__device__ __half g_A[(size_t)BATCH * KTOT];
__device__ __half g_W[(size_t)4 * HID * KTOT];

// ============================ merged pack kernel ============================
// A rows 0..8191 = [x|h0]. W row r = cblk*256 + gate*64 + hc, cblk = 64-hcol
// block (0..31), straight layout for N=256 cg2 subtiles.
__global__ void pack_all(const float* __restrict__ x, const float* __restrict__ h0,
                         const float* __restrict__ Wii, const float* __restrict__ Wif,
                         const float* __restrict__ Wig, const float* __restrict__ Wio,
                         const float* __restrict__ Whi, const float* __restrict__ Whf,
                         const float* __restrict__ Whg, const float* __restrict__ Who) {
    const float* Wi[4] = {Wii, Wif, Wig, Wio};
    const float* Wh[4] = {Whi, Whf, Whg, Who};
    const size_t n4 = (size_t)16384 * KTOT / 4;
    for (size_t i = (size_t)blockIdx.x * blockDim.x + threadIdx.x; i < n4;
         i += (size_t)gridDim.x * blockDim.x) {
        size_t idx = i * 4;
        size_t row = idx >> 12;
        int k = (int)(idx & 4095);
        const float* src;
        __half* dst;
        if (row < 8192) {
            src = (k < 2048) ? (x + row * 2048 + k) : (h0 + row * 2048 + (k - 2048));
            dst = g_A + idx;
        } else {
            size_t wrow = row - 8192;          // cblk*256 + gate*64 + hc
            int gate = (int)((wrow >> 6) & 3);
            size_t h = (wrow >> 8) * 64 + (wrow & 63);
            src = (k < 2048) ? (Wi[gate] + h * 2048 + k)
                             : (Wh[gate] + h * 2048 + (k - 2048));
            dst = g_W + (wrow << 12) + k;
        }
        float4 v = *(const float4*)src;
        *(__half2*)(dst)     = __floats2half2_rn(v.x, v.y);
        *(__half2*)(dst + 2) = __floats2half2_rn(v.z, v.w);
    }
}

// ======================================================================
// persistent cg2 tcgen05 + TMA (fp16), TMEM ping-pong
// ======================================================================
#define KT 64                       // 64 halves = 128B SW128 rows
#define STAGES 6
#define A_STG 16384                 // 128 rows x 128B
#define B_STG 16384                 // 128 rows x 128B
#define STAGE_BYTES (A_STG + B_STG) // 32KB
#define TC_SMEM_BYTES (2048 + STAGES * STAGE_BYTES)   // 198656

#if HAS_TCGEN05
__device__ __forceinline__ uint32_t smem_u32(const void* p) {
    uint32_t a;
    asm("{ .reg .u64 t; cvta.to.shared.u64 t, %1; cvt.u32.u64 %0, t; }" : "=r"(a) : "l"(p));
    return a;
}
#define MBAR_INIT(addr, cnt) \
    asm volatile("mbarrier.init.shared.b64 [%0], %1;" :: "r"(addr), "r"(cnt) : "memory")
#define MBAR_EXPECT_TX(addr, bytes) \
    asm volatile("mbarrier.arrive.expect_tx.shared.b64 _, [%0], %1;" :: "r"(addr), "r"(bytes) : "memory")
#define MBAR_WAIT(addr, par) do { \
    uint32_t _m = (addr); uint32_t _p = (par); uint32_t _d; \
    asm volatile("{\n\t.reg .pred p;\n\tmbarrier.try_wait.parity.acquire.cta.shared::cta.b64 p, [%1], %2;\n\tselp.b32 %0, 1, 0, p;\n\t}" \
        : "=r"(_d) : "r"(_m), "r"(_p) : "memory"); \
    if (!_d) { \
        asm volatile("{\n\t.reg .pred P1;\n\tWL_%=:\n\tmbarrier.try_wait.parity.acquire.cta.shared::cta.b64 P1, [%0], %1, 0x989680;\n\t@P1 bra.uni WD_%=;\n\tbra.uni WL_%=;\n\tWD_%=:\n\t}" \
            :: "r"(_m), "r"(_p) : "memory"); \
    } } while (0)
#define MBAR_WAIT_RLX(addr, par) do { \
    uint32_t _m = (addr); uint32_t _p = (par); uint32_t _d; \
    asm volatile("{\n\t.reg .pred p;\n\tmbarrier.try_wait.parity.relaxed.cta.shared::cta.b64 p, [%1], %2, 0x989680;\n\tselp.b32 %0, 1, 0, p;\n\t}" \
        : "=r"(_d) : "r"(_m), "r"(_p) : "memory"); \
    if (!_d) { \
        asm volatile("{\n\t.reg .pred P1;\n\tWL_%=:\n\tmbarrier.try_wait.parity.relaxed.cta.shared::cta.b64 P1, [%0], %1, 0x989680;\n\t@P1 bra.uni WD_%=;\n\tbra.uni WL_%=;\n\tWD_%=:\n\t}" \
            :: "r"(_m), "r"(_p) : "memory"); \
    } } while (0)
#define TC_ALLOC_CG2(smem_addr, n) \
    asm volatile("tcgen05.alloc.cta_group::2.sync.aligned.shared::cta.b32 [%0], %1;" :: "r"(smem_addr), "r"(n) : "memory")
#define TC_DEALLOC_CG2(tmem, n) \
    asm volatile("tcgen05.dealloc.cta_group::2.sync.aligned.b32 %0, %1;" :: "r"(tmem), "r"(n))
#define TC_RELINQ_CG2() asm volatile("tcgen05.relinquish_alloc_permit.cta_group::2.sync.aligned;")
#define TC_COMMIT_MC_CG2(mbar, mask) \
    asm volatile("tcgen05.commit.cta_group::2.mbarrier::arrive::one.shared::cluster.multicast::cluster.b64 [%0], %1;" \
                 :: "r"(mbar), "h"((uint16_t)(mask)) : "memory")
#define TC_FENCE_AFTER()   asm volatile("tcgen05.fence::after_thread_sync;" ::: "memory")
#define TC_FENCE_BEFORE()  asm volatile("tcgen05.fence::before_thread_sync;" ::: "memory")
#define TC_WAIT_LD()       asm volatile("tcgen05.wait::ld.sync.aligned;" ::: "memory")
#define CLUSTER_SYNC() do { \
    asm volatile("barrier.cluster.arrive.aligned;" ::: "memory"); \
    asm volatile("barrier.cluster.wait.aligned;" ::: "memory"); } while (0)
#define MBAR_ARRIVE_RANK0(addr) \
    asm volatile("{\n\t.reg .b32 ra;\n\tmapa.shared::cluster.u32 ra, %0, 0;\n\t" \
                 "mbarrier.arrive.shared::cluster.b64 _, [ra];\n\t}" \
                 :: "r"(addr) : "memory")

__device__ __forceinline__ void mma_f16_ss_cg2(uint32_t d, uint64_t a, uint64_t b,
                                               uint32_t idesc, uint32_t en) {
    asm volatile(
        "{\n\t.reg .pred p;\n\tsetp.ne.u32 p, %4, 0;\n\t"
        "tcgen05.mma.cta_group::2.kind::f16 [%0], %1, %2, %3, "
        "{%5, %5, %5, %5, %5, %5, %5, %5}, p;\n\t}"
        :: "r"(d), "l"(a), "l"(b), "r"(idesc), "r"(en), "r"(0u) : "memory");
}
#define LDTM_X16(r, addr) \
    asm volatile("tcgen05.ld.sync.aligned.32x32b.x16.b32 " \
        "{%0,%1,%2,%3,%4,%5,%6,%7,%8,%9,%10,%11,%12,%13,%14,%15}, [%16];" \
        : "=r"((r)[0]), "=r"((r)[1]), "=r"((r)[2]), "=r"((r)[3]), \
          "=r"((r)[4]), "=r"((r)[5]), "=r"((r)[6]), "=r"((r)[7]), \
          "=r"((r)[8]), "=r"((r)[9]), "=r"((r)[10]), "=r"((r)[11]), \
          "=r"((r)[12]), "=r"((r)[13]), "=r"((r)[14]), "=r"((r)[15]) \
        : "r"(addr))

__device__ __forceinline__ void tma2d_cg2(uint32_t dst, const void* map, int x, int y,
                                          uint32_t mbar) {
    asm volatile(
        "{\n\t.reg .b32 lb;\n\tand.b32 lb, %4, 0xFEFFFFFF;\n\t"
        "cp.async.bulk.tensor.2d.cta_group::2.shared::cluster.global.tile.mbarrier::complete_tx::bytes "
        "[%0], [%1, {%2, %3}], [lb];\n\t}"
        :: "r"(dst), "l"(map), "r"(x), "r"(y), "r"(mbar) : "memory");
}
__device__ __forceinline__ uint64_t make_desc(uint32_t addr) {
    return (uint64_t(2) << 61) | (uint64_t(1) << 46) | (uint64_t(64) << 32)
         | (uint64_t(1) << 16) | ((uint64_t)(addr >> 4) & 0x3FFF);
}
// idesc kind::f16: dtype=F32(1<<4), fp16 in, N=256 -> 32<<17, M=256 cg2 -> 16<<24
#define IDESC ((1u<<4) | (32u<<17) | (16u<<24))
#endif // HAS_TCGEN05

extern __shared__ char dsmem[];

__global__ void __launch_bounds__(320, 1) __cluster_dims__(2, 1, 1)
lstm_tc(const __grid_constant__ CUtensorMap tma_a,
        const __grid_constant__ CUtensorMap tma_b,
        const float* __restrict__ c0,
        const float* __restrict__ bii, const float* __restrict__ bif,
        const float* __restrict__ big, const float* __restrict__ bio,
        const float* __restrict__ bhi, const float* __restrict__ bhf,
        const float* __restrict__ bhg, const float* __restrict__ bho,
        float* __restrict__ out_h, float* __restrict__ out_c)
{
#if HAS_TCGEN05
    const uint32_t sb = smem_u32(dsmem);
    const uint32_t full0  = sb;          // 6 mbarriers
    const uint32_t empty0 = sb + 64;     // 6 mbarriers
    const uint32_t done0  = sb + 128;    // 2 (per TMEM half)
    const uint32_t free0  = sb + 144;    // 2 (per TMEM half, count=2)
    const uint32_t tptr   = sb + 192;
    const uint32_t tiles  = (sb + 1024 + 1023) & ~1023u;

    const int tid = threadIdx.x;
    const int warp = tid >> 5;
    const int lane = tid & 31;

    uint32_t crank;
    asm("mov.u32 %0, %%cluster_ctarank;" : "=r"(crank));
    const int rank = (int)(crank & 1);
    const int P = blockIdx.x >> 1;
    const int ntile_p = (NTILES - P + NPAIRS - 1) / NPAIRS;

    if (tid == 0) {
        #pragma unroll
        for (int s = 0; s < STAGES; s++) {
            MBAR_INIT(full0 + s * 8, 1);
            MBAR_INIT(empty0 + s * 8, 1);
        }
        MBAR_INIT(done0, 1);     MBAR_INIT(done0 + 8, 1);
        MBAR_INIT(free0, 2);     MBAR_INIT(free0 + 8, 2);
    }
    if (warp == 8) TC_ALLOC_CG2(tptr, 512);
    __syncthreads();
    CLUSTER_SYNC();

    uint32_t tmem;
    asm volatile("ld.shared.b32 %0, [%1];" : "=r"(tmem) : "r"(tptr));

    if (warp == 9 && lane == 0) {
        // ---------- producer: stream all (tile, sub, kt) stages ----------
        int eph[STAGES] = {0, 0, 0, 0, 0, 0};
        int gs = 0;
        for (int it = 0; it < ntile_p; it++) {
            const int tau = P + it * NPAIRS;
            const int m0  = (tau & 31) * 256;
            const int nb  = tau >> 5;
            const int arow = m0 + rank * 128;
            for (int sub = 0; sub < 2; sub++) {
                const int brow = (nb * 2 + sub) * 256 + rank * 128;
                for (int kt = 0; kt < 64; kt++, gs++) {
                    const int s = gs % STAGES;
                    if (gs >= STAGES) { MBAR_WAIT_RLX(empty0 + s * 8, eph[s]); eph[s] ^= 1; }
                    const uint32_t base = tiles + s * STAGE_BYTES;
                    if (rank == 0) MBAR_EXPECT_TX(full0 + s * 8, 2 * STAGE_BYTES);
                    tma2d_cg2(base, &tma_a, kt * KT, arow, full0 + s * 8);
                    tma2d_cg2(base + A_STG, &tma_b, kt * KT, brow, full0 + s * 8);
                }
            }
        }
    } else if (warp == 8 && lane == 0 && rank == 0) {
        // ---------- MMA issuer (leader): ping-pong TMEM halves ----------
        uint64_t ad[STAGES], bd[STAGES];
        #pragma unroll
        for (int s = 0; s < STAGES; s++) {
            ad[s] = make_desc(tiles + s * STAGE_BYTES);
            bd[s] = make_desc(tiles + s * STAGE_BYTES + A_STG);
        }
        int ph[STAGES] = {0, 0, 0, 0, 0, 0};
        int gs = 0;
        for (int it = 0; it < ntile_p; it++) {
            for (int sub = 0; sub < 2; sub++) {
                if (it > 0) MBAR_WAIT(free0 + sub * 8, (it - 1) & 1);
                const uint32_t dst = tmem + sub * 256;
                for (int kt = 0; kt < 64; kt++, gs++) {
                    const int s = gs % STAGES;
                    MBAR_WAIT_RLX(full0 + s * 8, ph[s]); ph[s] ^= 1;
                    #pragma unroll
                    for (int k = 0; k < 4; k++)
                        mma_f16_ss_cg2(dst, ad[s] + k * 2, bd[s] + k * 2, IDESC,
                                       (kt > 0 || k > 0) ? 1u : 0u);
                    if (kt == 63) TC_COMMIT_MC_CG2(done0 + sub * 8, 0x3);
                    TC_COMMIT_MC_CG2(empty0 + s * 8, 0x3);
                }
            }
        }
    }

    // ---------- epilogue: warps 0-7, drain sub-tiles alternately ----------
    if (warp < 8) {
        const int qp = warp & 3;
        const int hh = warp >> 2;
        for (int it = 0; it < ntile_p; it++) {
            const int tau = P + it * NPAIRS;
            const int m0  = (tau & 31) * 256;
            const int nb  = tau >> 5;
            const int row = m0 + rank * 128 + qp * 32 + lane;
            for (int sub = 0; sub < 2; sub++) {
                const int nh0 = (nb * 2 + sub) * 64;
                const size_t rb = (size_t)row * HID + nh0;
                const uint32_t tb = tmem + sub * 256;
                MBAR_WAIT(done0 + sub * 8, it & 1);
                TC_FENCE_AFTER();

                #pragma unroll
                for (int j = 0; j < 2; j++) {
                    const int jc = hh * 2 + j;     // 0..3, 16 hcols each
                    uint32_t ri[16], rf[16], rg[16], ro[16];
                    LDTM_X16(ri, tb + 0   + jc * 16);
                    LDTM_X16(rf, tb + 64  + jc * 16);
                    LDTM_X16(rg, tb + 128 + jc * 16);
                    LDTM_X16(ro, tb + 192 + jc * 16);
                    TC_WAIT_LD();
                    #pragma unroll
                    for (int e = 0; e < 16; e++) {
                        const int col = nh0 + jc * 16 + e;
                        const float gi = __uint_as_float(ri[e]) + __ldg(&bii[col]) + __ldg(&bhi[col]);
                        const float gf = __uint_as_float(rf[e]) + __ldg(&bif[col]) + __ldg(&bhf[col]);
                        const float gg = __uint_as_float(rg[e]) + __ldg(&big[col]) + __ldg(&bhg[col]);
                        const float go = __uint_as_float(ro[e]) + __ldg(&bio[col]) + __ldg(&bho[col]);
                        const float itv = fsig(gi);
                        const float ft  = fsig(gf);
                        const float gt  = ftanh(gg);
                        const float ot  = fsig(go);
                        const float cv = ft * __ldg(&c0[rb + jc * 16 + e]) + itv * gt;
                        out_h[rb + jc * 16 + e] = ot * ftanh(cv);
                        out_c[rb + jc * 16 + e] = cv;
                    }
                }
                TC_FENCE_BEFORE();
                asm volatile("bar.sync 1, 256;" ::: "memory");
                if (warp == 0 && lane == 0) MBAR_ARRIVE_RANK0(free0 + sub * 8);
            }
        }
    }

    __syncthreads();
    if (warp == 8) {
        TC_RELINQ_CG2();
        TC_DEALLOC_CG2(tmem, 512);
    }
    CLUSTER_SYNC();
#endif // HAS_TCGEN05
}

// ======================================================================
// Fallback: legacy mma.sync tf32 kernel (known-good)
// ======================================================================
#define FMT 128
#define FNT 32
#define FKT 32
#define SPAD 36
#define A_BUF_F (FMT * SPAD)
#define B_BUF_F (4 * FNT * SPAD)
#define B_BASE_F (2 * A_BUF_F)
#define FB_SMEM_BYTES ((2 * A_BUF_F + 2 * B_BUF_F) * (int)sizeof(float))

__device__ __forceinline__ void mma_tf32(float* d, const uint32_t* a, const uint32_t* b) {
    asm volatile(
        "mma.sync.aligned.m16n8k8.row.col.f32.tf32.tf32.f32 "
        "{%0,%1,%2,%3},{%4,%5,%6,%7},{%8,%9},{%0,%1,%2,%3};"
        : "+f"(d[0]), "+f"(d[1]), "+f"(d[2]), "+f"(d[3])
        : "r"(a[0]), "r"(a[1]), "r"(a[2]), "r"(a[3]), "r"(b[0]), "r"(b[1]));
}
__device__ __forceinline__ void cp16f(void* dst, const void* src) {
    uint32_t s = (uint32_t)__cvta_generic_to_shared(dst);
    asm volatile("cp.async.ca.shared.global [%0],[%1],16;" ::"r"(s), "l"(src));
}

__global__ void __launch_bounds__(256, 1)
lstm_fused_tf32(
    const float* __restrict__ x, const float* __restrict__ h0, const float* __restrict__ c0,
    const float* __restrict__ Wx0, const float* __restrict__ Wx1,
    const float* __restrict__ Wx2, const float* __restrict__ Wx3,
    const float* __restrict__ Wh0, const float* __restrict__ Wh1,
    const float* __restrict__ Wh2, const float* __restrict__ Wh3,
    const float* __restrict__ bx0, const float* __restrict__ bx1,
    const float* __restrict__ bx2, const float* __restrict__ bx3,
    const float* __restrict__ bh0, const float* __restrict__ bh1,
    const float* __restrict__ bh2, const float* __restrict__ bh3,
    float* __restrict__ out_h, float* __restrict__ out_c)
{
    float* smem = (float*)dsmem;
    const int t = threadIdx.x;
    const int m_base = blockIdx.y * FMT;
    const int n_base = blockIdx.x * FNT;

    const float* Wx[4] = {Wx0, Wx1, Wx2, Wx3};
    const float* Wh[4] = {Wh0, Wh1, Wh2, Wh3};

    const int lrow = t >> 3;
    const int lc4  = (t & 7) * 4;

    auto load_tile = [&](int buf, int kt) {
        const int k0 = kt * FKT;
        const bool first = (k0 < 2048);
        const float* Asrc = first ? x : h0;
        const int kofs = first ? k0 : (k0 - 2048);
        #pragma unroll
        for (int i = 0; i < 4; i++) {
            int r = i * 32 + lrow;
            cp16f(&smem[buf * A_BUF_F + r * SPAD + lc4],
                  Asrc + (size_t)(m_base + r) * 2048 + kofs + lc4);
        }
        #pragma unroll
        for (int g = 0; g < 4; g++) {
            const float* W = first ? Wx[g] : Wh[g];
            cp16f(&smem[B_BASE_F + buf * B_BUF_F + g * (FNT * SPAD) + lrow * SPAD + lc4],
                  W + (size_t)(n_base + lrow) * 2048 + kofs + lc4);
        }
        asm volatile("cp.async.commit_group;");
    };

    const int warp = t >> 5;
    const int lane = t & 31;
    const int wm = warp & 3;
    const int wn = warp >> 2;
    const int gid = lane >> 2;
    const int tig = lane & 3;

    float acc[4][2][2][4];
    #pragma unroll
    for (int g = 0; g < 4; g++)
        #pragma unroll
        for (int mi = 0; mi < 2; mi++)
            #pragma unroll
            for (int ni = 0; ni < 2; ni++)
                #pragma unroll
                for (int e = 0; e < 4; e++) acc[g][mi][ni][e] = 0.f;

    const int NKT = KTOT / FKT;
    int buf = 0;
    load_tile(0, 0);

    for (int kt = 0; kt < NKT; kt++) {
        asm volatile("cp.async.wait_group 0;");
        __syncthreads();
        if (kt + 1 < NKT) load_tile(buf ^ 1, kt + 1);

        const float* As = &smem[buf * A_BUF_F];
        const float* Bs = &smem[B_BASE_F + buf * B_BUF_F];

        #pragma unroll
        for (int kk = 0; kk < FKT / 8; kk++) {
            const int kb = kk * 8;
            uint32_t a[2][4];
            #pragma unroll
            for (int mi = 0; mi < 2; mi++) {
                const float* Ab = As + (wm * 32 + mi * 16 + gid) * SPAD + kb + tig;
                a[mi][0] = f2tf32(Ab[0]);
                a[mi][1] = f2tf32(Ab[8 * SPAD]);
                a[mi][2] = f2tf32(Ab[4]);
                a[mi][3] = f2tf32(Ab[8 * SPAD + 4]);
            }
            uint32_t bfr[4][2][2];
            #pragma unroll
            for (int g = 0; g < 4; g++) {
                #pragma unroll
                for (int ni = 0; ni < 2; ni++) {
                    const float* Bb = Bs + g * (FNT * SPAD) + (wn * 16 + ni * 8 + gid) * SPAD + kb + tig;
                    bfr[g][ni][0] = f2tf32(Bb[0]);
                    bfr[g][ni][1] = f2tf32(Bb[4]);
                }
            }
            #pragma unroll
            for (int g = 0; g < 4; g++)
                #pragma unroll
                for (int mi = 0; mi < 2; mi++)
                    #pragma unroll
                    for (int ni = 0; ni < 2; ni++)
                        mma_tf32(acc[g][mi][ni], a[mi], bfr[g][ni]);
        }
        __syncthreads();
        buf ^= 1;
    }

    const int mrow = m_base + wm * 32;
    const int ncol = n_base + wn * 16;
    #pragma unroll
    for (int mi = 0; mi < 2; mi++) {
        #pragma unroll
        for (int ni = 0; ni < 2; ni++) {
            #pragma unroll
            for (int half = 0; half < 2; half++) {
                const int col = ncol + ni * 8 + tig * 2 + half;
                const float bi = __ldg(&bx0[col]) + __ldg(&bh0[col]);
                const float bf = __ldg(&bx1[col]) + __ldg(&bh1[col]);
                const float bg = __ldg(&bx2[col]) + __ldg(&bh2[col]);
                const float bo = __ldg(&bx3[col]) + __ldg(&bh3[col]);
                #pragma unroll
                for (int rh = 0; rh < 2; rh++) {
                    const int row = mrow + mi * 16 + gid + rh * 8;
                    const int e = rh * 2 + half;
                    const float gi = acc[0][mi][ni][e] + bi;
                    const float gf = acc[1][mi][ni][e] + bf;
                    const float gg = acc[2][mi][ni][e] + bg;
                    const float go = acc[3][mi][ni][e] + bo;
                    const float it = 1.f / (1.f + expf(-gi));
                    const float ft = 1.f / (1.f + expf(-gf));
                    const float gt = tanhf(gg);
                    const float ot = 1.f / (1.f + expf(-go));
                    const size_t off = (size_t)row * HID + col;
                    const float cv = ft * __ldg(&c0[off]) + it * gt;
                    out_h[off] = ot * tanhf(cv);
                    out_c[off] = cv;
                }
            }
        }
    }
}

// ============================ launch ============================
typedef CUresult (*tmap_encode_fn)(
    CUtensorMap*, CUtensorMapDataType, cuuint32_t, void*,
    const cuuint64_t*, const cuuint64_t*, const cuuint32_t*, const cuuint32_t*,
    CUtensorMapInterleave, CUtensorMapSwizzle, CUtensorMapL2promotion,
    CUtensorMapFloatOOBfill);

extern "C" void kernel_launch(void* const* d_in, const int* in_sizes, int n_in,
                              void* d_out, int out_size) {
    const float* x   = (const float*)d_in[0];
    const float* h0  = (const float*)d_in[1];
    const float* c0  = (const float*)d_in[2];
    const float* Wii = (const float*)d_in[3];  const float* bii = (const float*)d_in[4];
    const float* Wif = (const float*)d_in[5];  const float* bif = (const float*)d_in[6];
    const float* Wig = (const float*)d_in[7];  const float* big = (const float*)d_in[8];
    const float* Wio = (const float*)d_in[9];  const float* bio = (const float*)d_in[10];
    const float* Whi = (const float*)d_in[11]; const float* bhi = (const float*)d_in[12];
    const float* Whf = (const float*)d_in[13]; const float* bhf = (const float*)d_in[14];
    const float* Whg = (const float*)d_in[15]; const float* bhg = (const float*)d_in[16];
    const float* Who = (const float*)d_in[17]; const float* bho = (const float*)d_in[18];

    float* out_h = (float*)d_out;
    float* out_c = out_h + (size_t)BATCH * HID;

    static int use_tc = -1;
    static CUtensorMap tmapA, tmapB;
    if (use_tc < 0) {
        use_tc = 0;
        cudaFuncAttributes attr;
        if (cudaFuncGetAttributes(&attr, lstm_tc) == cudaSuccess && attr.numRegs > 32) {
            void* fn = nullptr;
            cudaDriverEntryPointQueryResult qres;
            if (cudaGetDriverEntryPoint("cuTensorMapEncodeTiled", &fn,
                                        cudaEnableDefault, &qres) == cudaSuccess && fn) {
                void *pA = nullptr, *pW = nullptr;
                cudaGetSymbolAddress(&pA, g_A);
                cudaGetSymbolAddress(&pW, g_W);
                cuuint64_t dims[2] = {KTOT, 8192};
                cuuint64_t strides[1] = {(cuuint64_t)KTOT * 2};
                cuuint32_t box[2] = {64, 128};   // both A and B: 128 rows x 128B
                cuuint32_t es[2] = {1, 1};
                tmap_encode_fn enc = (tmap_encode_fn)fn;
                CUresult r1 = enc(&tmapA, CU_TENSOR_MAP_DATA_TYPE_FLOAT16, 2, pA,
                                  dims, strides, box, es,
                                  CU_TENSOR_MAP_INTERLEAVE_NONE,
                                  CU_TENSOR_MAP_SWIZZLE_128B,
                                  CU_TENSOR_MAP_L2_PROMOTION_L2_128B,
                                  CU_TENSOR_MAP_FLOAT_OOB_FILL_NONE);
                CUresult r2 = enc(&tmapB, CU_TENSOR_MAP_DATA_TYPE_FLOAT16, 2, pW,
                                  dims, strides, box, es,
                                  CU_TENSOR_MAP_INTERLEAVE_NONE,
                                  CU_TENSOR_MAP_SWIZZLE_128B,
                                  CU_TENSOR_MAP_L2_PROMOTION_L2_128B,
                                  CU_TENSOR_MAP_FLOAT_OOB_FILL_NONE);
                if (r1 == CUDA_SUCCESS && r2 == CUDA_SUCCESS && pA && pW)
                    use_tc = 1;
            }
        }
        if (use_tc) {
            cudaFuncSetAttribute(lstm_tc, cudaFuncAttributeMaxDynamicSharedMemorySize,
                                 TC_SMEM_BYTES);
        } else {
            cudaFuncSetAttribute(lstm_fused_tf32,
                                 cudaFuncAttributeMaxDynamicSharedMemorySize, FB_SMEM_BYTES);
        }
    }

    if (use_tc) {
        pack_all<<<4096, 256>>>(x, h0, Wii, Wif, Wig, Wio, Whi, Whf, Whg, Who);
        dim3 grid(2 * NPAIRS, 1);   // 148 persistent CTAs = 74 cg2 pairs
        lstm_tc<<<grid, 320, TC_SMEM_BYTES>>>(tmapA, tmapB, c0,
            bii, bif, big, bio, bhi, bhf, bhg, bho, out_h, out_c);
    } else {
        dim3 grid(HID / FNT, BATCH / FMT);
        lstm_fused_tf32<<<grid, 256, FB_SMEM_BYTES>>>(
            x, h0, c0,
            Wii, Wif, Wig, Wio,
            Whi, Whf, Whg, Who,
            bii, bif, big, bio,
            bhi, bhf, bhg, bho,
            out_h, out_c);
    }
}

// round 12
// speedup vs baseline: 1.0101x; 1.0101x over previous
#include <cuda_runtime.h>
#include <cuda.h>
#include <cuda_fp16.h>
#include <cstdint>
#include <math.h>

// LSTM cell: gates = [x|h0] @ [Wx|Wh]^T + b, fused elementwise epilogue.
// R12: persistent cg2 tcgen05 fp16; gmem holds PRE-SWIZZLED 16KB tile chunks
// so stages load via flat cp.async.bulk (no TMA row-generation). Per-CTA
// local full barriers + forwarder warp relaying completion to the leader.

#define BATCH 8192
#define HID   2048
#define KTOT  4096
#define NTILES 512      // 32 m-blocks x 16 n-blocks
#define NPAIRS 74

#if defined(__CUDA_ARCH__) && defined(__CUDA_ARCH_FEAT_SM103_ALL)
#define HAS_TCGEN05 1
#else
#define HAS_TCGEN05 0
#endif

__device__ __forceinline__ uint32_t f2tf32(float x) {
    uint32_t u; asm("cvt.rna.tf32.f32 %0, %1;" : "=r"(u) : "f"(x)); return u;
}
__device__ __forceinline__ float ex2a(float x) {
    float y; asm("ex2.approx.f32 %0, %1;" : "=f"(y) : "f"(x)); return y;
}
__device__ __forceinline__ float rcpa(float x) {
    float y; asm("rcp.approx.f32 %0, %1;" : "=f"(y) : "f"(x)); return y;
}
__device__ __forceinline__ float fsig(float x) {
    return rcpa(1.0f + ex2a(-1.4426950408889634f * x));
}
__device__ __forceinline__ float ftanh(float x) {
    return fmaf(2.0f, rcpa(1.0f + ex2a(-2.8853900817779268f * x)), -1.0f);
}
__host__ __device__ __forceinline__ uint32_t swzb(uint32_t off) {
    return off ^ ((off >> 3) & 0x70);
}

// -------- scratch: PRE-SWIZZLED chunk images (16KB per (blk, kt)) --------
// g_A chunk (mblk*64 + kt): swizzled 128 rows x 128B of A rows mblk*128..+127, k kt*64..+63
// g_W chunk (pairblk*128 + kt*2 + sub): swizzled image of W storage rows
//   (pairblk*2+sub)*128..+127 (cg2-ordered), k kt*64..+63
__device__ __half g_A[(size_t)BATCH * KTOT];
__device__ __half g_W[(size_t)4 * HID * KTOT];

// ============================ merged pack kernel ============================
__global__ void pack_all(const float* __restrict__ x, const float* __restrict__ h0,
                         const float* __restrict__ Wii, const float* __restrict__ Wif,
                         const float* __restrict__ Wig, const float* __restrict__ Wio,
                         const float* __restrict__ Whi, const float* __restrict__ Whf,
                         const float* __restrict__ Whg, const float* __restrict__ Who) {
    const float* Wi[4] = {Wii, Wif, Wig, Wio};
    const float* Wh[4] = {Whi, Whf, Whg, Who};
    const size_t n4 = (size_t)16384 * KTOT / 4;
    for (size_t i = (size_t)blockIdx.x * blockDim.x + threadIdx.x; i < n4;
         i += (size_t)gridDim.x * blockDim.x) {
        size_t idx = i * 4;
        size_t row = idx >> 12;        // logical storage row
        int k = (int)(idx & 4095);
        const int kt = k >> 6;
        const int c  = k & 63;         // half index within 64-wide k-chunk
        const float* src;
        __half* dst;
        if (row < 8192) {              // A: row = batch row
            src = (k < 2048) ? (x + row * 2048 + k) : (h0 + row * 2048 + (k - 2048));
            const int mblk = (int)(row >> 7), r = (int)(row & 127);
            const size_t chunk = (size_t)mblk * 64 + kt;
            dst = g_A + chunk * 8192 + (swzb((uint32_t)(r * 128 + c * 2)) >> 1);
        } else {                       // W: cg2-ordered storage row
            size_t wrow = row - 8192;
            int q = (int)(wrow & 511);
            int nblk = (int)(wrow >> 9);
            int b = q >> 7;
            int gate = ((b & 1) << 1) | (b >> 1);
            size_t h = (size_t)nblk * 128 + (q & 127);
            src = (k < 2048) ? (Wi[gate] + h * 2048 + k)
                             : (Wh[gate] + h * 2048 + (k - 2048));
            const int wblk = (int)(wrow >> 7), r = (int)(wrow & 127);
            const size_t chunk = (size_t)(wblk >> 1) * 128 + kt * 2 + (wblk & 1);
            dst = g_W + chunk * 8192 + (swzb((uint32_t)(r * 128 + c * 2)) >> 1);
        }
        float4 v = *(const float4*)src;
        *(__half2*)(dst)     = __floats2half2_rn(v.x, v.y);
        *(__half2*)(dst + 2) = __floats2half2_rn(v.z, v.w);
    }
}

// ======================================================================
// persistent cg2 tcgen05 + flat bulk-copy pipeline (fp16)
// ======================================================================
#define KT 64
#define STAGES 4
#define A_STG 16384
#define B_STG 32768
#define STAGE_BYTES (A_STG + B_STG)   // 48KB
#define TC_SMEM_BYTES (2048 + STAGES * STAGE_BYTES)   // 198656

#if HAS_TCGEN05
__device__ __forceinline__ uint32_t smem_u32(const void* p) {
    uint32_t a;
    asm("{ .reg .u64 t; cvta.to.shared.u64 t, %1; cvt.u32.u64 %0, t; }" : "=r"(a) : "l"(p));
    return a;
}
#define MBAR_INIT(addr, cnt) \
    asm volatile("mbarrier.init.shared.b64 [%0], %1;" :: "r"(addr), "r"(cnt) : "memory")
#define MBAR_EXPECT_TX(addr, bytes) \
    asm volatile("mbarrier.arrive.expect_tx.shared.b64 _, [%0], %1;" :: "r"(addr), "r"(bytes) : "memory")
#define MBAR_WAIT(addr, par) do { \
    uint32_t _m = (addr); uint32_t _p = (par); uint32_t _d; \
    asm volatile("{\n\t.reg .pred p;\n\tmbarrier.try_wait.parity.acquire.cta.shared::cta.b64 p, [%1], %2;\n\tselp.b32 %0, 1, 0, p;\n\t}" \
        : "=r"(_d) : "r"(_m), "r"(_p) : "memory"); \
    if (!_d) { \
        asm volatile("{\n\t.reg .pred P1;\n\tWL_%=:\n\tmbarrier.try_wait.parity.acquire.cta.shared::cta.b64 P1, [%0], %1, 0x989680;\n\t@P1 bra.uni WD_%=;\n\tbra.uni WL_%=;\n\tWD_%=:\n\t}" \
            :: "r"(_m), "r"(_p) : "memory"); \
    } } while (0)
#define MBAR_WAIT_RLX(addr, par) do { \
    uint32_t _m = (addr); uint32_t _p = (par); uint32_t _d; \
    asm volatile("{\n\t.reg .pred p;\n\tmbarrier.try_wait.parity.relaxed.cta.shared::cta.b64 p, [%1], %2, 0x989680;\n\tselp.b32 %0, 1, 0, p;\n\t}" \
        : "=r"(_d) : "r"(_m), "r"(_p) : "memory"); \
    if (!_d) { \
        asm volatile("{\n\t.reg .pred P1;\n\tWL_%=:\n\tmbarrier.try_wait.parity.relaxed.cta.shared::cta.b64 P1, [%0], %1, 0x989680;\n\t@P1 bra.uni WD_%=;\n\tbra.uni WL_%=;\n\tWD_%=:\n\t}" \
            :: "r"(_m), "r"(_p) : "memory"); \
    } } while (0)
#define TC_ALLOC_CG2(smem_addr, n) \
    asm volatile("tcgen05.alloc.cta_group::2.sync.aligned.shared::cta.b32 [%0], %1;" :: "r"(smem_addr), "r"(n) : "memory")
#define TC_DEALLOC_CG2(tmem, n) \
    asm volatile("tcgen05.dealloc.cta_group::2.sync.aligned.b32 %0, %1;" :: "r"(tmem), "r"(n))
#define TC_RELINQ_CG2() asm volatile("tcgen05.relinquish_alloc_permit.cta_group::2.sync.aligned;")
#define TC_COMMIT_MC_CG2(mbar, mask) \
    asm volatile("tcgen05.commit.cta_group::2.mbarrier::arrive::one.shared::cluster.multicast::cluster.b64 [%0], %1;" \
                 :: "r"(mbar), "h"((uint16_t)(mask)) : "memory")
#define TC_FENCE_AFTER()   asm volatile("tcgen05.fence::after_thread_sync;" ::: "memory")
#define TC_FENCE_BEFORE()  asm volatile("tcgen05.fence::before_thread_sync;" ::: "memory")
#define TC_WAIT_LD()       asm volatile("tcgen05.wait::ld.sync.aligned;" ::: "memory")
#define CLUSTER_SYNC() do { \
    asm volatile("barrier.cluster.arrive.aligned;" ::: "memory"); \
    asm volatile("barrier.cluster.wait.aligned;" ::: "memory"); } while (0)
#define MBAR_ARRIVE_RANK0(addr) \
    asm volatile("{\n\t.reg .b32 ra;\n\tmapa.shared::cluster.u32 ra, %0, 0;\n\t" \
                 "mbarrier.arrive.shared::cluster.b64 _, [ra];\n\t}" \
                 :: "r"(addr) : "memory")

__device__ __forceinline__ void mma_f16_ss_cg2(uint32_t d, uint64_t a, uint64_t b,
                                               uint32_t idesc, uint32_t en) {
    asm volatile(
        "{\n\t.reg .pred p;\n\tsetp.ne.u32 p, %4, 0;\n\t"
        "tcgen05.mma.cta_group::2.kind::f16 [%0], %1, %2, %3, "
        "{%5, %5, %5, %5, %5, %5, %5, %5}, p;\n\t}"
        :: "r"(d), "l"(a), "l"(b), "r"(idesc), "r"(en), "r"(0u) : "memory");
}
#define LDTM_X16(r, addr) \
    asm volatile("tcgen05.ld.sync.aligned.32x32b.x16.b32 " \
        "{%0,%1,%2,%3,%4,%5,%6,%7,%8,%9,%10,%11,%12,%13,%14,%15}, [%16];" \
        : "=r"((r)[0]), "=r"((r)[1]), "=r"((r)[2]), "=r"((r)[3]), \
          "=r"((r)[4]), "=r"((r)[5]), "=r"((r)[6]), "=r"((r)[7]), \
          "=r"((r)[8]), "=r"((r)[9]), "=r"((r)[10]), "=r"((r)[11]), \
          "=r"((r)[12]), "=r"((r)[13]), "=r"((r)[14]), "=r"((r)[15]) \
        : "r"(addr))

// flat bulk copy gmem -> local smem, completion on local mbarrier
__device__ __forceinline__ void blkcp(uint32_t dst, const void* src, uint32_t bytes,
                                      uint32_t mbar) {
    asm volatile(
        "cp.async.bulk.shared::cluster.global.mbarrier::complete_tx::bytes "
        "[%0], [%1], %2, [%3];"
        :: "r"(dst), "l"(src), "r"(bytes), "r"(mbar) : "memory");
}
__device__ __forceinline__ uint64_t make_desc(uint32_t addr) {
    return (uint64_t(2) << 61) | (uint64_t(1) << 46) | (uint64_t(64) << 32)
         | (uint64_t(1) << 16) | ((uint64_t)(addr >> 4) & 0x3FFF);
}
#define IDESC ((1u<<4) | (32u<<17) | (16u<<24))
#endif // HAS_TCGEN05

extern __shared__ char dsmem[];

__global__ void __launch_bounds__(352, 1) __cluster_dims__(2, 1, 1)
lstm_tc(const float* __restrict__ c0,
        const float* __restrict__ bii, const float* __restrict__ bif,
        const float* __restrict__ big, const float* __restrict__ bio,
        const float* __restrict__ bhi, const float* __restrict__ bhf,
        const float* __restrict__ bhg, const float* __restrict__ bho,
        float* __restrict__ out_h, float* __restrict__ out_c)
{
#if HAS_TCGEN05
    const uint32_t sb = smem_u32(dsmem);
    const uint32_t full0  = sb;          // 4 local full (tx-based)
    const uint32_t empty0 = sb + 64;     // 4 empty
    const uint32_t doneb  = sb + 128;
    const uint32_t freeb  = sb + 136;    // count=2
    const uint32_t fullx0 = sb + 160;    // 4 leader-side full (count=2)
    const uint32_t tptr   = sb + 224;
    const uint32_t tiles  = (sb + 1024 + 1023) & ~1023u;

    const int tid = threadIdx.x;
    const int warp = tid >> 5;
    const int lane = tid & 31;

    uint32_t crank;
    asm("mov.u32 %0, %%cluster_ctarank;" : "=r"(crank));
    const int rank = (int)(crank & 1);
    const int P = blockIdx.x >> 1;
    const int ntile_p = (NTILES - P + NPAIRS - 1) / NPAIRS;
    const int nstg = ntile_p * 64;

    if (tid == 0) {
        #pragma unroll
        for (int s = 0; s < STAGES; s++) {
            MBAR_INIT(full0 + s * 8, 1);
            MBAR_INIT(empty0 + s * 8, 1);
            MBAR_INIT(fullx0 + s * 8, 2);
        }
        MBAR_INIT(doneb, 1);
        MBAR_INIT(freeb, 2);
    }
    if (warp == 8) TC_ALLOC_CG2(tptr, 512);
    __syncthreads();
    CLUSTER_SYNC();

    uint32_t tmem;
    asm volatile("ld.shared.b32 %0, [%1];" : "=r"(tmem) : "r"(tptr));

    if (warp == 9 && lane == 0) {
        // ---------- producer: flat bulk copies from pre-swizzled chunks ----------
        int eph[STAGES] = {0, 0, 0, 0};
        int gs = 0;
        for (int it = 0; it < ntile_p; it++) {
            const int tau = P + it * NPAIRS;
            const int mblk = (tau & 31) * 2 + rank;       // A 128-row block
            const int nblk = tau >> 5;
            const __half* asrc = g_A + ((size_t)mblk * 64) * 8192;
            const __half* bsrc = g_W + ((size_t)(nblk * 2 + rank) * 128) * 8192;
            for (int kt = 0; kt < 64; kt++, gs++) {
                const int s = gs & 3;
                if (gs >= STAGES) { MBAR_WAIT_RLX(empty0 + s * 8, eph[s]); eph[s] ^= 1; }
                const uint32_t base = tiles + s * STAGE_BYTES;
                MBAR_EXPECT_TX(full0 + s * 8, STAGE_BYTES);
                blkcp(base,         asrc + (size_t)kt * 8192,      A_STG, full0 + s * 8);
                blkcp(base + A_STG, bsrc + (size_t)kt * 2 * 8192,  B_STG, full0 + s * 8);
            }
        }
    } else if (warp == 10 && lane == 0) {
        // ---------- forwarder: relay local full -> leader fullx ----------
        int fph[STAGES] = {0, 0, 0, 0};
        for (int gs = 0; gs < nstg; gs++) {
            const int s = gs & 3;
            MBAR_WAIT(full0 + s * 8, fph[s]); fph[s] ^= 1;
            MBAR_ARRIVE_RANK0(fullx0 + s * 8);
        }
    } else if (warp == 8 && lane == 0 && rank == 0) {
        // ---------- MMA issuer (leader) ----------
        uint64_t ad[STAGES], bd[STAGES];
        #pragma unroll
        for (int s = 0; s < STAGES; s++) {
            ad[s] = make_desc(tiles + s * STAGE_BYTES);
            bd[s] = make_desc(tiles + s * STAGE_BYTES + A_STG);
        }
        int ph[STAGES] = {0, 0, 0, 0};
        for (int it = 0; it < ntile_p; it++) {
            if (it > 0) MBAR_WAIT(freeb, (it - 1) & 1);
            for (int kt = 0; kt < 64; kt++) {
                const int s = kt & 3;
                MBAR_WAIT_RLX(fullx0 + s * 8, ph[s]); ph[s] ^= 1;
                #pragma unroll
                for (int k = 0; k < 4; k++) {
                    const uint32_t en = (kt > 0 || k > 0) ? 1u : 0u;
                    mma_f16_ss_cg2(tmem,       ad[s] + k * 2, bd[s] + k * 2,        IDESC, en);
                    mma_f16_ss_cg2(tmem + 256, ad[s] + k * 2, bd[s] + 1024 + k * 2, IDESC, en);
                }
                if (kt == 63) TC_COMMIT_MC_CG2(doneb, 0x3);
                TC_COMMIT_MC_CG2(empty0 + s * 8, 0x3);
            }
        }
    }

    // ---------- epilogue: warps 0-7 ----------
    if (warp < 8) {
        const int qp = warp & 3;
        const int hh = warp >> 2;
        for (int it = 0; it < ntile_p; it++) {
            const int tau = P + it * NPAIRS;
            const int m0  = (tau & 31) * 256;
            const int nb  = tau >> 5;
            const int nh0 = nb * 128;
            MBAR_WAIT(doneb, it & 1);
            TC_FENCE_AFTER();

            const int row = m0 + rank * 128 + qp * 32 + lane;
            const size_t rb = (size_t)row * HID + nh0;

            #pragma unroll
            for (int j = 0; j < 4; j++) {
                const int jc = hh * 4 + j;
                uint32_t ri[16], rf[16], rg[16], ro[16];
                LDTM_X16(ri, tmem + 0   + jc * 16);
                LDTM_X16(rf, tmem + 128 + jc * 16);
                LDTM_X16(rg, tmem + 256 + jc * 16);
                LDTM_X16(ro, tmem + 384 + jc * 16);
                TC_WAIT_LD();
                #pragma unroll
                for (int e = 0; e < 16; e++) {
                    const int col = nh0 + jc * 16 + e;
                    const float gi = __uint_as_float(ri[e]) + __ldg(&bii[col]) + __ldg(&bhi[col]);
                    const float gf = __uint_as_float(rf[e]) + __ldg(&bif[col]) + __ldg(&bhf[col]);
                    const float gg = __uint_as_float(rg[e]) + __ldg(&big[col]) + __ldg(&bhg[col]);
                    const float go = __uint_as_float(ro[e]) + __ldg(&bio[col]) + __ldg(&bho[col]);
                    const float itv = fsig(gi);
                    const float ft  = fsig(gf);
                    const float gt  = ftanh(gg);
                    const float ot  = fsig(go);
                    const float cv = ft * __ldg(&c0[rb + jc * 16 + e]) + itv * gt;
                    out_h[rb + jc * 16 + e] = ot * ftanh(cv);
                    out_c[rb + jc * 16 + e] = cv;
                }
            }
            TC_FENCE_BEFORE();
            asm volatile("bar.sync 1, 256;" ::: "memory");
            if (warp == 0 && lane == 0) MBAR_ARRIVE_RANK0(freeb);
        }
    }

    __syncthreads();
    if (warp == 8) {
        TC_RELINQ_CG2();
        TC_DEALLOC_CG2(tmem, 512);
    }
    CLUSTER_SYNC();
#endif // HAS_TCGEN05
}

// ======================================================================
// Fallback: legacy mma.sync tf32 kernel (known-good)
// ======================================================================
#define FMT 128
#define FNT 32
#define FKT 32
#define SPAD 36
#define A_BUF_F (FMT * SPAD)
#define B_BUF_F (4 * FNT * SPAD)
#define B_BASE_F (2 * A_BUF_F)
#define FB_SMEM_BYTES ((2 * A_BUF_F + 2 * B_BUF_F) * (int)sizeof(float))

__device__ __forceinline__ void mma_tf32(float* d, const uint32_t* a, const uint32_t* b) {
    asm volatile(
        "mma.sync.aligned.m16n8k8.row.col.f32.tf32.tf32.f32 "
        "{%0,%1,%2,%3},{%4,%5,%6,%7},{%8,%9},{%0,%1,%2,%3};"
        : "+f"(d[0]), "+f"(d[1]), "+f"(d[2]), "+f"(d[3])
        : "r"(a[0]), "r"(a[1]), "r"(a[2]), "r"(a[3]), "r"(b[0]), "r"(b[1]));
}
__device__ __forceinline__ void cp16f(void* dst, const void* src) {
    uint32_t s = (uint32_t)__cvta_generic_to_shared(dst);
    asm volatile("cp.async.ca.shared.global [%0],[%1],16;" ::"r"(s), "l"(src));
}

__global__ void __launch_bounds__(256, 1)
lstm_fused_tf32(
    const float* __restrict__ x, const float* __restrict__ h0, const float* __restrict__ c0,
    const float* __restrict__ Wx0, const float* __restrict__ Wx1,
    const float* __restrict__ Wx2, const float* __restrict__ Wx3,
    const float* __restrict__ Wh0, const float* __restrict__ Wh1,
    const float* __restrict__ Wh2, const float* __restrict__ Wh3,
    const float* __restrict__ bx0, const float* __restrict__ bx1,
    const float* __restrict__ bx2, const float* __restrict__ bx3,
    const float* __restrict__ bh0, const float* __restrict__ bh1,
    const float* __restrict__ bh2, const float* __restrict__ bh3,
    float* __restrict__ out_h, float* __restrict__ out_c)
{
    float* smem = (float*)dsmem;
    const int t = threadIdx.x;
    const int m_base = blockIdx.y * FMT;
    const int n_base = blockIdx.x * FNT;

    const float* Wx[4] = {Wx0, Wx1, Wx2, Wx3};
    const float* Wh[4] = {Wh0, Wh1, Wh2, Wh3};

    const int lrow = t >> 3;
    const int lc4  = (t & 7) * 4;

    auto load_tile = [&](int buf, int kt) {
        const int k0 = kt * FKT;
        const bool first = (k0 < 2048);
        const float* Asrc = first ? x : h0;
        const int kofs = first ? k0 : (k0 - 2048);
        #pragma unroll
        for (int i = 0; i < 4; i++) {
            int r = i * 32 + lrow;
            cp16f(&smem[buf * A_BUF_F + r * SPAD + lc4],
                  Asrc + (size_t)(m_base + r) * 2048 + kofs + lc4);
        }
        #pragma unroll
        for (int g = 0; g < 4; g++) {
            const float* W = first ? Wx[g] : Wh[g];
            cp16f(&smem[B_BASE_F + buf * B_BUF_F + g * (FNT * SPAD) + lrow * SPAD + lc4],
                  W + (size_t)(n_base + lrow) * 2048 + kofs + lc4);
        }
        asm volatile("cp.async.commit_group;");
    };

    const int warp = t >> 5;
    const int lane = t & 31;
    const int wm = warp & 3;
    const int wn = warp >> 2;
    const int gid = lane >> 2;
    const int tig = lane & 3;

    float acc[4][2][2][4];
    #pragma unroll
    for (int g = 0; g < 4; g++)
        #pragma unroll
        for (int mi = 0; mi < 2; mi++)
            #pragma unroll
            for (int ni = 0; ni < 2; ni++)
                #pragma unroll
                for (int e = 0; e < 4; e++) acc[g][mi][ni][e] = 0.f;

    const int NKT = KTOT / FKT;
    int buf = 0;
    load_tile(0, 0);

    for (int kt = 0; kt < NKT; kt++) {
        asm volatile("cp.async.wait_group 0;");
        __syncthreads();
        if (kt + 1 < NKT) load_tile(buf ^ 1, kt + 1);

        const float* As = &smem[buf * A_BUF_F];
        const float* Bs = &smem[B_BASE_F + buf * B_BUF_F];

        #pragma unroll
        for (int kk = 0; kk < FKT / 8; kk++) {
            const int kb = kk * 8;
            uint32_t a[2][4];
            #pragma unroll
            for (int mi = 0; mi < 2; mi++) {
                const float* Ab = As + (wm * 32 + mi * 16 + gid) * SPAD + kb + tig;
                a[mi][0] = f2tf32(Ab[0]);
                a[mi][1] = f2tf32(Ab[8 * SPAD]);
                a[mi][2] = f2tf32(Ab[4]);
                a[mi][3] = f2tf32(Ab[8 * SPAD + 4]);
            }
            uint32_t bfr[4][2][2];
            #pragma unroll
            for (int g = 0; g < 4; g++) {
                #pragma unroll
                for (int ni = 0; ni < 2; ni++) {
                    const float* Bb = Bs + g * (FNT * SPAD) + (wn * 16 + ni * 8 + gid) * SPAD + kb + tig;
                    bfr[g][ni][0] = f2tf32(Bb[0]);
                    bfr[g][ni][1] = f2tf32(Bb[4]);
                }
            }
            #pragma unroll
            for (int g = 0; g < 4; g++)
                #pragma unroll
                for (int mi = 0; mi < 2; mi++)
                    #pragma unroll
                    for (int ni = 0; ni < 2; ni++)
                        mma_tf32(acc[g][mi][ni], a[mi], bfr[g][ni]);
        }
        __syncthreads();
        buf ^= 1;
    }

    const int mrow = m_base + wm * 32;
    const int ncol = n_base + wn * 16;
    #pragma unroll
    for (int mi = 0; mi < 2; mi++) {
        #pragma unroll
        for (int ni = 0; ni < 2; ni++) {
            #pragma unroll
            for (int half = 0; half < 2; half++) {
                const int col = ncol + ni * 8 + tig * 2 + half;
                const float bi = __ldg(&bx0[col]) + __ldg(&bh0[col]);
                const float bf = __ldg(&bx1[col]) + __ldg(&bh1[col]);
                const float bg = __ldg(&bx2[col]) + __ldg(&bh2[col]);
                const float bo = __ldg(&bx3[col]) + __ldg(&bh3[col]);
                #pragma unroll
                for (int rh = 0; rh < 2; rh++) {
                    const int row = mrow + mi * 16 + gid + rh * 8;
                    const int e = rh * 2 + half;
                    const float gi = acc[0][mi][ni][e] + bi;
                    const float gf = acc[1][mi][ni][e] + bf;
                    const float gg = acc[2][mi][ni][e] + bg;
                    const float go = acc[3][mi][ni][e] + bo;
                    const float it = 1.f / (1.f + expf(-gi));
                    const float ft = 1.f / (1.f + expf(-gf));
                    const float gt = tanhf(gg);
                    const float ot = 1.f / (1.f + expf(-go));
                    const size_t off = (size_t)row * HID + col;
                    const float cv = ft * __ldg(&c0[off]) + it * gt;
                    out_h[off] = ot * tanhf(cv);
                    out_c[off] = cv;
                }
            }
        }
    }
}

// ============================ launch ============================
extern "C" void kernel_launch(void* const* d_in, const int* in_sizes, int n_in,
                              void* d_out, int out_size) {
    const float* x   = (const float*)d_in[0];
    const float* h0  = (const float*)d_in[1];
    const float* c0  = (const float*)d_in[2];
    const float* Wii = (const float*)d_in[3];  const float* bii = (const float*)d_in[4];
    const float* Wif = (const float*)d_in[5];  const float* bif = (const float*)d_in[6];
    const float* Wig = (const float*)d_in[7];  const float* big = (const float*)d_in[8];
    const float* Wio = (const float*)d_in[9];  const float* bio = (const float*)d_in[10];
    const float* Whi = (const float*)d_in[11]; const float* bhi = (const float*)d_in[12];
    const float* Whf = (const float*)d_in[13]; const float* bhf = (const float*)d_in[14];
    const float* Whg = (const float*)d_in[15]; const float* bhg = (const float*)d_in[16];
    const float* Who = (const float*)d_in[17]; const float* bho = (const float*)d_in[18];

    float* out_h = (float*)d_out;
    float* out_c = out_h + (size_t)BATCH * HID;

    static int use_tc = -1;
    if (use_tc < 0) {
        use_tc = 0;
        cudaFuncAttributes attr;
        if (cudaFuncGetAttributes(&attr, lstm_tc) == cudaSuccess && attr.numRegs > 32)
            use_tc = 1;
        if (use_tc) {
            cudaFuncSetAttribute(lstm_tc, cudaFuncAttributeMaxDynamicSharedMemorySize,
                                 TC_SMEM_BYTES);
        } else {
            cudaFuncSetAttribute(lstm_fused_tf32,
                                 cudaFuncAttributeMaxDynamicSharedMemorySize, FB_SMEM_BYTES);
        }
    }

    if (use_tc) {
        pack_all<<<4096, 256>>>(x, h0, Wii, Wif, Wig, Wio, Whi, Whf, Whg, Who);
        dim3 grid(2 * NPAIRS, 1);
        lstm_tc<<<grid, 352, TC_SMEM_BYTES>>>(c0,
            bii, bif, big, bio, bhi, bhf, bhg, bho, out_h, out_c);
    } else {
        dim3 grid(HID / FNT, BATCH / FMT);
        lstm_fused_tf32<<<grid, 256, FB_SMEM_BYTES>>>(
            x, h0, c0,
            Wii, Wif, Wig, Wio,
            Whi, Whf, Whg, Who,
            bii, bif, big, bio,
            bhi, bhf, bhg, bho,
            out_h, out_c);
    }
}